// round 2
// baseline (speedup 1.0000x reference)
#include <cuda_runtime.h>

// peepLSTM: B=128 T=512 I=128 H=512 NC=100
// Strategy:
//  - xg = emb[idx] @ Wx is a gather from G = emb@Wx+b (only 101 distinct rows).
//  - Recurrence only needs cg_f, cg_i per step (o only at t=T-1; c_tilde has no
//    recurrent term; h never feeds back).
//  - One persistent kernel, 128 CTAs, global-memory barrier per step.
//  - Inner GEMM per CTA: M=64(b-half) x N=16(8 f-cols + 8 i-cols) x K=512,
//    weights stationary in smem, C double-buffered in global (L2-resident),
//    packed fp32 FMAs via fma.rn.f32x2.

#define BB   128
#define TT   512
#define II   128
#define HH   512
#define NCC  100
#define NCTA 128
#define NTHR 256
#define WPAD 516   // 512 + 4 pad -> conflict-free [col][k] smem layout

__device__ float d_G[4 * 101 * HH];      // gate-major: f,i,o,c
__device__ float d_WocT[HH * HH];        // Woc transposed: [h][k]
__device__ float d_Cbuf[2][BB * HH];
__device__ float d_hf[BB * HH];
__device__ unsigned d_arrive = 0;
__device__ unsigned d_release = 0;

typedef unsigned long long u64;

__device__ __forceinline__ void ffma2(u64& d, u64 a, u64 b) {
    asm("fma.rn.f32x2 %0, %1, %2, %0;" : "+l"(d) : "l"(a), "l"(b));
}
__device__ __forceinline__ float2 unpk(u64 v) {
    float2 r;
    asm("mov.b64 {%0, %1}, %2;" : "=f"(r.x), "=f"(r.y) : "l"(v));
    return r;
}
__device__ __forceinline__ float sigm(float x) {
    return __fdividef(1.f, 1.f + __expf(-x));
}

// Monotonic-generation grid barrier (no reset needed across graph replays).
__device__ __forceinline__ void grid_sync() {
    __syncthreads();
    if (threadIdx.x == 0) {
        __threadfence();
        unsigned old = atomicAdd(&d_arrive, 1u);
        unsigned target = old / NCTA + 1u;
        if ((old & (NCTA - 1)) == (NCTA - 1)) atomicAdd(&d_release, 1u);
        unsigned v;
        do {
            asm volatile("ld.global.acquire.gpu.u32 %0, [%1];"
                         : "=r"(v) : "l"(&d_release) : "memory");
        } while ((int)(v - target) < 0);
        __threadfence();
    }
    __syncthreads();
}

__global__ __launch_bounds__(NTHR, 1)
void peep_kernel(const int* __restrict__ x, const float* __restrict__ emb,
                 const float* __restrict__ Wfx, const float* __restrict__ Wfc,
                 const float* __restrict__ bf,
                 const float* __restrict__ Wix, const float* __restrict__ Wic,
                 const float* __restrict__ bi,
                 const float* __restrict__ Wox, const float* __restrict__ Woc,
                 const float* __restrict__ bo,
                 const float* __restrict__ Wcx, const float* __restrict__ bc,
                 const float* __restrict__ Wph, const float* __restrict__ bp,
                 float* __restrict__ out)
{
    __shared__ float s_Wf[8 * WPAD];
    __shared__ float s_Wi[8 * WPAD];
    __shared__ float s_hf[HH];
    __shared__ float s_p[128];
    __shared__ float s_red[2];

    const int tid = threadIdx.x;
    const int cta = blockIdx.x;

    // ---------------- Phase 0: precompute G, WocT, stage smem weights -------
    {
        int gt = cta * NTHR + tid;
        // G[g][row][h] = b_g[h] + sum_i emb[row][i] * Wgx[i][h]   (4-wide in h)
        for (int q = gt; q < 4 * 101 * (HH / 4); q += NCTA * NTHR) {
            int g = q / (101 * (HH / 4));
            int rem = q - g * (101 * (HH / 4));
            int row = rem / (HH / 4);
            int h4 = (rem - row * (HH / 4)) * 4;
            const float* Wg = (g == 0) ? Wfx : ((g == 1) ? Wix : ((g == 2) ? Wox : Wcx));
            const float* bg = (g == 0) ? bf  : ((g == 1) ? bi  : ((g == 2) ? bo  : bc));
            float4 acc = make_float4(bg[h4], bg[h4 + 1], bg[h4 + 2], bg[h4 + 3]);
            const float* er = emb + row * II;
#pragma unroll 4
            for (int i = 0; i < II; i++) {
                float e = er[i];
                float4 w = *(const float4*)(Wg + i * HH + h4);
                acc.x = fmaf(e, w.x, acc.x);
                acc.y = fmaf(e, w.y, acc.y);
                acc.z = fmaf(e, w.z, acc.z);
                acc.w = fmaf(e, w.w, acc.w);
            }
            *(float4*)(d_G + g * 101 * HH + row * HH + h4) = acc;
        }
        // WocT[h][k] = Woc[k][h]
        for (int j = gt; j < HH * HH; j += NCTA * NTHR) {
            int k = j >> 9;
            int h = j & (HH - 1);
            d_WocT[h * HH + k] = Woc[k * HH + h];
        }
    }

    const int bhalf = cta & 1;
    const int hc = cta >> 1;          // 0..63
    const int h0 = hc * 8;
    // stage Wfc/Wic column slices [h0, h0+8) transposed to [col][k]
    for (int j = tid; j < 8 * HH; j += NTHR) {
        int c = j >> 9;
        int k = j & (HH - 1);
        s_Wf[c * WPAD + k] = Wfc[k * HH + h0 + c];
        s_Wi[c * WPAD + k] = Wic[k * HH + h0 + c];
    }
    grid_sync();

    // ---------------- Phase 1: the recurrence -------------------------------
    const int b  = bhalf * 64 + (tid >> 2);
    const int cq = tid & 3;
    const int hA = h0 + cq * 2;       // this thread owns h columns hA, hA+1
    const ulonglong2* pf0 = (const ulonglong2*)(s_Wf + (cq * 2    ) * WPAD);
    const ulonglong2* pf1 = (const ulonglong2*)(s_Wf + (cq * 2 + 1) * WPAD);
    const ulonglong2* pi0 = (const ulonglong2*)(s_Wi + (cq * 2    ) * WPAD);
    const ulonglong2* pi1 = (const ulonglong2*)(s_Wi + (cq * 2 + 1) * WPAD);

    for (int t = 0; t < TT; t++) {
        const int rd = t & 1, wr = rd ^ 1;
        const int iv = x[b * TT + t];
        const float r = (iv > 0) ? 1.f : 0.f;
        const float2 gf = *(const float2*)(d_G + 0 * 101 * HH + iv * HH + hA);
        const float2 gi = *(const float2*)(d_G + 1 * 101 * HH + iv * HH + hA);
        const float2 gc = *(const float2*)(d_G + 3 * 101 * HH + iv * HH + hA);

        float cgf0 = 0.f, cgf1 = 0.f, cgi0 = 0.f, cgi1 = 0.f;
        float cold0 = 0.f, cold1 = 0.f;
        float cgo0 = 0.f, cgo1 = 0.f;

        if (t > 0) {
            const float* crowf = d_Cbuf[rd] + b * HH;
            const ulonglong2* cr = (const ulonglong2*)crowf;
            u64 af0 = 0, af1 = 0, ai0 = 0, ai1 = 0;
#pragma unroll 4
            for (int k4 = 0; k4 < HH / 4; k4++) {
                ulonglong2 c2 = cr[k4];
                ulonglong2 w0 = pf0[k4];
                ffma2(af0, c2.x, w0.x); ffma2(af0, c2.y, w0.y);
                ulonglong2 w1 = pf1[k4];
                ffma2(af1, c2.x, w1.x); ffma2(af1, c2.y, w1.y);
                ulonglong2 w2 = pi0[k4];
                ffma2(ai0, c2.x, w2.x); ffma2(ai0, c2.y, w2.y);
                ulonglong2 w3 = pi1[k4];
                ffma2(ai1, c2.x, w3.x); ffma2(ai1, c2.y, w3.y);
            }
            float2 u;
            u = unpk(af0); cgf0 = u.x + u.y;
            u = unpk(af1); cgf1 = u.x + u.y;
            u = unpk(ai0); cgi0 = u.x + u.y;
            u = unpk(ai1); cgi1 = u.x + u.y;
            cold0 = crowf[hA];
            cold1 = crowf[hA + 1];

            if (t == TT - 1) {  // o-gate GEMM only needed at the last step
                u64 ao0 = 0, ao1 = 0;
                const ulonglong2* q0 = (const ulonglong2*)(d_WocT + hA * HH);
                const ulonglong2* q1 = (const ulonglong2*)(d_WocT + (hA + 1) * HH);
#pragma unroll 4
                for (int k4 = 0; k4 < HH / 4; k4++) {
                    ulonglong2 c2 = cr[k4];
                    ulonglong2 w0 = q0[k4];
                    ffma2(ao0, c2.x, w0.x); ffma2(ao0, c2.y, w0.y);
                    ulonglong2 w1 = q1[k4];
                    ffma2(ao1, c2.x, w1.x); ffma2(ao1, c2.y, w1.y);
                }
                u = unpk(ao0); cgo0 = u.x + u.y;
                u = unpk(ao1); cgo1 = u.x + u.y;
            }
        }

        float f0 = sigm(gf.x + cgf0), f1 = sigm(gf.y + cgf1);
        float i0 = sigm(gi.x + cgi0), i1 = sigm(gi.y + cgi1);
        float t0 = sigm(gc.x),        t1 = sigm(gc.y);
        float Cn0 = (t0 * i0 + cold0 * f0) * r;
        float Cn1 = (t1 * i1 + cold1 * f1) * r;
        *(float2*)(d_Cbuf[wr] + b * HH + hA) = make_float2(Cn0, Cn1);

        if (t == TT - 1) {
            const float2 go = *(const float2*)(d_G + 2 * 101 * HH + iv * HH + hA);
            float o0 = sigm(go.x + cgo0), o1 = sigm(go.y + cgo1);
            *(float2*)(d_hf + b * HH + hA) =
                make_float2(tanhf(Cn0) * o0, tanhf(Cn1) * o1);
        }
        grid_sync();
    }

    // ---------------- Phase 2: projection + log_softmax (CTA = batch row) ---
    for (int h = tid; h < HH; h += NTHR) s_hf[h] = d_hf[cta * HH + h];
    __syncthreads();
    if (tid < NCC) {
        float acc = bp[tid];
#pragma unroll 8
        for (int h = 0; h < HH; h++)
            acc = fmaf(s_hf[h], Wph[h * NCC + tid], acc);
        s_p[tid] = acc;
    }
    __syncthreads();
    if (tid == 0) {
        float mx = -1e30f;
        for (int c = 0; c < NCC; c++) mx = fmaxf(mx, s_p[c]);
        float s = 0.f;
        for (int c = 0; c < NCC; c++) s += expf(s_p[c] - mx);
        s_red[0] = mx;
        s_red[1] = logf(s);
    }
    __syncthreads();
    if (tid < NCC)
        out[cta * NCC + tid] = s_p[tid] - s_red[0] - s_red[1];
}

extern "C" void kernel_launch(void* const* d_in, const int* in_sizes, int n_in,
                              void* d_out, int out_size) {
    (void)in_sizes; (void)n_in; (void)out_size;
    const int*   x   = (const int*)  d_in[0];
    const float* emb = (const float*)d_in[1];
    const float* Wfx = (const float*)d_in[2];
    const float* Wfc = (const float*)d_in[3];
    const float* bf  = (const float*)d_in[4];
    const float* Wix = (const float*)d_in[5];
    const float* Wic = (const float*)d_in[6];
    const float* bi  = (const float*)d_in[7];
    const float* Wox = (const float*)d_in[8];
    const float* Woc = (const float*)d_in[9];
    const float* bo  = (const float*)d_in[10];
    const float* Wcx = (const float*)d_in[11];
    const float* bc  = (const float*)d_in[12];
    const float* Wph = (const float*)d_in[13];
    const float* bp  = (const float*)d_in[14];
    peep_kernel<<<NCTA, NTHR>>>(x, emb, Wfx, Wfc, bf, Wix, Wic, bi,
                                Wox, Woc, bo, Wcx, bc, Wph, bp, (float*)d_out);
}

// round 5
// speedup vs baseline: 1.6626x; 1.6626x over previous
#include <cuda_runtime.h>

// peepLSTM B=128 T=512 I=128 H=512 NC=100 — round 3
// Decomposition: 128 CTAs = 8 row-groups (16 b-rows) x 16 col-groups (32 h).
// Each CTA: cg tile [16 b x 64 col(32 f + 32 i)] x K=512 per step.
// Weights stationary in smem (128KB). C staged per step into smem (34KB,
// interleaved [k4][m] layout, pad 17 -> all GEMM LDS are 1-wavefront).
// Register tile 4m x 2n, k-split 2. Barrier = per-row-group (fan-in 16).

#define BB   128
#define TT   512
#define II   128
#define HH   512
#define NCC  100
#define NCTA 128
#define NTHR 256

#define OFF_W   0
#define SZ_W    (128*1024)          // 128 k4 * 64 slots * 16B
#define OFF_C   (SZ_W)
#define SZ_C    (128*17*16)         // [k4][17] float4, pad slot 16
#define OFF_RED (OFF_C + SZ_C)
#define SZ_RED  (128*8*8)           // 128 threads * 8 u64
#define OFF_CG  (OFF_RED + SZ_RED)
#define SZ_CG   (16*64*4)
#define SMEM_BYTES (OFF_CG + SZ_CG) // 178176

__device__ float d_G[4 * 101 * HH];     // gate-major f,i,o,c
__device__ float d_WocT[HH * HH];       // Woc transposed [h][k]
__device__ float d_Cbuf[2][BB * HH];
__device__ float d_hf[BB * HH];
__device__ unsigned d_full[64];         // [0]=arrive, [32]=release (padded)
__device__ unsigned d_garr[8 * 32];     // group arrive, 128B stride
__device__ unsigned d_grel[8 * 32];     // group release

typedef unsigned long long u64;

__device__ __forceinline__ void ffma2(u64& d, u64 a, u64 b) {
    asm("fma.rn.f32x2 %0, %1, %2, %0;" : "+l"(d) : "l"(a), "l"(b));
}
__device__ __forceinline__ float2 unpk(u64 v) {
    float2 r;
    asm("mov.b64 {%0, %1}, %2;" : "=f"(r.x), "=f"(r.y) : "l"(v));
    return r;
}
__device__ __forceinline__ float sigm(float x) {
    return __fdividef(1.f, 1.f + __expf(-x));
}

// monotonic full-grid barrier (replay-safe)
__device__ __forceinline__ void full_sync() {
    __syncthreads();
    if (threadIdx.x == 0) {
        __threadfence();
        unsigned old = atomicAdd(&d_full[0], 1u);
        unsigned target = old / NCTA + 1u;
        if ((old % NCTA) == (unsigned)(NCTA - 1)) atomicAdd(&d_full[32], 1u);
        unsigned v;
        do {
            asm volatile("ld.global.acquire.gpu.u32 %0, [%1];"
                         : "=r"(v) : "l"(&d_full[32]) : "memory");
        } while ((int)(v - target) < 0);
        __threadfence();
    }
    __syncthreads();
}

__global__ __launch_bounds__(NTHR, 1)
void peep_kernel(const int* __restrict__ x, const float* __restrict__ emb,
                 const float* __restrict__ Wfx, const float* __restrict__ Wfc,
                 const float* __restrict__ bf,
                 const float* __restrict__ Wix, const float* __restrict__ Wic,
                 const float* __restrict__ bi,
                 const float* __restrict__ Wox, const float* __restrict__ Woc,
                 const float* __restrict__ bo,
                 const float* __restrict__ Wcx, const float* __restrict__ bc,
                 const float* __restrict__ Wph, const float* __restrict__ bp,
                 float* __restrict__ out)
{
    extern __shared__ char smem[];
    ulonglong2* sW = (ulonglong2*)(smem + OFF_W);
    ulonglong2* sC = (ulonglong2*)(smem + OFF_C);
    u64*        sR = (u64*)(smem + OFF_RED);
    float*     sCG = (float*)(smem + OFF_CG);

    const int tid = threadIdx.x;
    const int cta = blockIdx.x;
    const int rg  = cta & 7;          // row group
    const int cgp = cta >> 3;         // col group
    const int b0  = rg * 16;
    const int h_base = cgp * 32;

    // ---------------- Phase 0: G = emb@Wx+b (gather table), WocT, smem W ----
    {
        int gt = cta * NTHR + tid;
        for (int q = gt; q < 4 * 101 * (HH / 4); q += NCTA * NTHR) {
            int g = q / (101 * (HH / 4));
            int rem = q - g * (101 * (HH / 4));
            int row = rem / (HH / 4);
            int h4 = (rem - row * (HH / 4)) * 4;
            const float* Wg = (g == 0) ? Wfx : ((g == 1) ? Wix : ((g == 2) ? Wox : Wcx));
            const float* bg = (g == 0) ? bf  : ((g == 1) ? bi  : ((g == 2) ? bo  : bc));
            float4 acc = make_float4(bg[h4], bg[h4 + 1], bg[h4 + 2], bg[h4 + 3]);
            const float* er = emb + row * II;
#pragma unroll 4
            for (int i = 0; i < II; i++) {
                float e = er[i];
                float4 w = *(const float4*)(Wg + i * HH + h4);
                acc.x = fmaf(e, w.x, acc.x);
                acc.y = fmaf(e, w.y, acc.y);
                acc.z = fmaf(e, w.z, acc.z);
                acc.w = fmaf(e, w.w, acc.w);
            }
            *(float4*)(d_G + g * 101 * HH + row * HH + h4) = acc;
        }
        for (int j = gt; j < HH * HH; j += NCTA * NTHR) {
            int k = j >> 9;
            int h = j & (HH - 1);
            d_WocT[h * HH + k] = Woc[k * HH + h];
        }
    }
    // fill stationary weight smem: sW[k4][j][sn] = float4 of Wgate[k..k+3][h]
    for (int q = tid; q < 128 * 64; q += NTHR) {
        int k4 = q >> 6, c = q & 63;
        int snc = c >> 1, jc = c & 1;
        int gate = c >> 5, hl = c & 31;
        const float* Wsrc = gate ? Wic : Wfc;
        int k = k4 * 4, h = h_base + hl;
        float4 v;
        v.x = Wsrc[(k + 0) * HH + h];
        v.y = Wsrc[(k + 1) * HH + h];
        v.z = Wsrc[(k + 2) * HH + h];
        v.w = Wsrc[(k + 3) * HH + h];
        ((float4*)sW)[k4 * 64 + jc * 32 + snc] = v;
    }
    full_sync();

    // ---------------- Phase 1: recurrence -----------------------------------
    const int ks  = tid >> 7;         // k-slice 0/1
    const int sid = tid & 127;
    const int sm  = sid & 3;          // m-lane (rows sm, 4+sm, 8+sm, 12+sm)
    const int sn  = sid >> 2;         // n-lane (cols 2sn, 2sn+1)
    // epilogue mapping: 2 h per thread
    const int ebl = tid >> 4;
    const int eh2 = (tid & 15) * 2;
    const int eb  = b0 + ebl;
    const int ehg = h_base + eh2;

    unsigned tgt = 0;  // only thread 0 uses

    for (int t = 0; t < TT; t++) {
        const int rd = t & 1, wr = rd ^ 1;
        // prefetch (independent of barrier)
        const int iv = x[eb * TT + t];
        const float rr = (iv > 0) ? 1.f : 0.f;
        const float2 gf2 = *(const float2*)(d_G + 0 * 101 * HH + iv * HH + ehg);
        const float2 gi2 = *(const float2*)(d_G + 1 * 101 * HH + iv * HH + ehg);
        const float2 gc2 = *(const float2*)(d_G + 3 * 101 * HH + iv * HH + ehg);

        if (t > 0) {
            if (tid == 0) {
                unsigned v;
                do {
                    asm volatile("ld.global.acquire.gpu.u32 %0, [%1];"
                                 : "=r"(v) : "l"(&d_grel[rg * 32]) : "memory");
                } while ((int)(v - tgt) < 0);
                __threadfence();
            }
            __syncthreads();
            // stage C rows [b0, b0+16) into interleaved smem
            {
                const float4* src = (const float4*)(d_Cbuf[rd] + b0 * HH);
                float4* dst = (float4*)sC;
#pragma unroll
                for (int jq = 0; jq < 8; jq++) {
                    int q = tid + jq * NTHR;
                    int m = q >> 7, k4 = q & 127;
                    dst[k4 * 17 + m] = src[m * 128 + k4];
                }
            }
            __syncthreads();
            // GEMM: acc[i*2+j] = cg(m = i*4+sm, col = 2sn+j) over K-half ks
            u64 acc[8];
#pragma unroll
            for (int q = 0; q < 8; q++) acc[q] = 0;
            const ulonglong2* cp = sC + (ks * 64) * 17;
            const ulonglong2* wp = sW + (ks * 64) * 64 + sn;
#pragma unroll 4
            for (int k4 = 0; k4 < 64; k4++) {
                ulonglong2 w0 = wp[0], w1 = wp[32];
                ulonglong2 c0 = cp[sm],     c1 = cp[4 + sm];
                ulonglong2 c2 = cp[8 + sm], c3 = cp[12 + sm];
                ffma2(acc[0], c0.x, w0.x); ffma2(acc[0], c0.y, w0.y);
                ffma2(acc[1], c0.x, w1.x); ffma2(acc[1], c0.y, w1.y);
                ffma2(acc[2], c1.x, w0.x); ffma2(acc[2], c1.y, w0.y);
                ffma2(acc[3], c1.x, w1.x); ffma2(acc[3], c1.y, w1.y);
                ffma2(acc[4], c2.x, w0.x); ffma2(acc[4], c2.y, w0.y);
                ffma2(acc[5], c2.x, w1.x); ffma2(acc[5], c2.y, w1.y);
                ffma2(acc[6], c3.x, w0.x); ffma2(acc[6], c3.y, w0.y);
                ffma2(acc[7], c3.x, w1.x); ffma2(acc[7], c3.y, w1.y);
                cp += 17; wp += 64;
            }
            if (ks == 1) {
                u64* r = sR + sid * 8;
#pragma unroll
                for (int q = 0; q < 8; q++) r[q] = acc[q];
            }
            __syncthreads();
            if (ks == 0) {
                const u64* r = sR + sid * 8;
#pragma unroll
                for (int q = 0; q < 8; q++) {
                    u64 o;
                    asm("add.rn.f32x2 %0, %1, %2;" : "=l"(o) : "l"(acc[q]), "l"(r[q]));
                    float2 v = unpk(o);
                    int i = q >> 1, j = q & 1;
                    sCG[(i * 4 + sm) * 64 + sn * 2 + j] = v.x + v.y;
                }
            }
            __syncthreads();
        }
        // epilogue: 2 (b,h) cells per thread
        float cgf0 = 0.f, cgf1 = 0.f, cgi0 = 0.f, cgi1 = 0.f;
        float cold0 = 0.f, cold1 = 0.f;
        if (t > 0) {
            cgf0 = sCG[ebl * 64 + eh2];
            cgf1 = sCG[ebl * 64 + eh2 + 1];
            cgi0 = sCG[ebl * 64 + 32 + eh2];
            cgi1 = sCG[ebl * 64 + 32 + eh2 + 1];
            const float* cc = (const float*)(sC + (ehg >> 2) * 17 + ebl);
            cold0 = cc[ehg & 3];
            cold1 = cc[(ehg & 3) + 1];
        }
        float f0 = sigm(gf2.x + cgf0), f1 = sigm(gf2.y + cgf1);
        float i0 = sigm(gi2.x + cgi0), i1 = sigm(gi2.y + cgi1);
        float t0v = sigm(gc2.x),       t1v = sigm(gc2.y);
        float Cn0 = (t0v * i0 + cold0 * f0) * rr;
        float Cn1 = (t1v * i1 + cold1 * f1) * rr;
        *(float2*)(d_Cbuf[wr] + eb * HH + ehg) = make_float2(Cn0, Cn1);

        if (t == TT - 1) {   // o-gate + final h (once)
            float ao0 = 0.f, ao1 = 0.f;
            const float4* w0p = (const float4*)(d_WocT + ehg * HH);
            const float4* w1p = (const float4*)(d_WocT + (ehg + 1) * HH);
#pragma unroll 4
            for (int k4 = 0; k4 < 128; k4++) {
                float4 c4 = ((const float4*)sC)[k4 * 17 + ebl];
                float4 wa = w0p[k4], wb = w1p[k4];
                ao0 = fmaf(c4.x, wa.x, fmaf(c4.y, wa.y, fmaf(c4.z, wa.z, fmaf(c4.w, wa.w, ao0))));
                ao1 = fmaf(c4.x, wb.x, fmaf(c4.y, wb.y, fmaf(c4.z, wb.z, fmaf(c4.w, wb.w, ao1))));
            }
            const float2 go2 = *(const float2*)(d_G + 2 * 101 * HH + iv * HH + ehg);
            float o0 = sigm(go2.x + ao0), o1 = sigm(go2.y + ao1);
            *(float2*)(d_hf + eb * HH + ehg) =
                make_float2(tanhf(Cn0) * o0, tanhf(Cn1) * o1);
        }
        __syncthreads();
        if (tid == 0) {
            __threadfence();
            unsigned old = atomicAdd(&d_garr[rg * 32], 1u);
            if ((old & 15u) == 15u) atomicAdd(&d_grel[rg * 32], 1u);
            tgt = old / 16u + 1u;
        }
    }

    full_sync();

    // ---------------- Phase 2: projection + log_softmax (CTA = batch row) ---
    float* s_hf = (float*)(smem);
    float* s_p  = (float*)(smem + 4096);
    float* s_rd = (float*)(smem + 8192);
    for (int h = tid; h < HH; h += NTHR) s_hf[h] = d_hf[cta * HH + h];
    __syncthreads();
    if (tid < NCC) {
        float acc = bp[tid];
#pragma unroll 8
        for (int h = 0; h < HH; h++)
            acc = fmaf(s_hf[h], Wph[h * NCC + tid], acc);
        s_p[tid] = acc;
    }
    __syncthreads();
    if (tid == 0) {
        float mx = -1e30f;
        for (int c = 0; c < NCC; c++) mx = fmaxf(mx, s_p[c]);
        float s = 0.f;
        for (int c = 0; c < NCC; c++) s += expf(s_p[c] - mx);
        s_rd[0] = mx;
        s_rd[1] = logf(s);
    }
    __syncthreads();
    if (tid < NCC)
        out[cta * NCC + tid] = s_p[tid] - s_rd[0] - s_rd[1];
}

extern "C" void kernel_launch(void* const* d_in, const int* in_sizes, int n_in,
                              void* d_out, int out_size) {
    (void)in_sizes; (void)n_in; (void)out_size;
    const int*   x   = (const int*)  d_in[0];
    const float* emb = (const float*)d_in[1];
    const float* Wfx = (const float*)d_in[2];
    const float* Wfc = (const float*)d_in[3];
    const float* bf  = (const float*)d_in[4];
    const float* Wix = (const float*)d_in[5];
    const float* Wic = (const float*)d_in[6];
    const float* bi  = (const float*)d_in[7];
    const float* Wox = (const float*)d_in[8];
    const float* Woc = (const float*)d_in[9];
    const float* bo  = (const float*)d_in[10];
    const float* Wcx = (const float*)d_in[11];
    const float* bc  = (const float*)d_in[12];
    const float* Wph = (const float*)d_in[13];
    const float* bp  = (const float*)d_in[14];
    cudaFuncSetAttribute(peep_kernel,
                         cudaFuncAttributeMaxDynamicSharedMemorySize, SMEM_BYTES);
    peep_kernel<<<NCTA, NTHR, SMEM_BYTES>>>(x, emb, Wfx, Wfc, bf, Wix, Wic, bi,
                                            Wox, Woc, bo, Wcx, bc, Wph, bp,
                                            (float*)d_out);
}